// round 16
// baseline (speedup 1.0000x reference)
#include <cuda_runtime.h>
#include <cuda_bf16.h>

// ROI mean-pool, v16: cross-plane register-staged pipeline, re-shaped for
// occupancy: 4 segments x 20, 320 producer threads, block 352, <=46 regs.
//
// fmap: [64,256,80,80] f32   boxes: [64,100,4]   out: [64,100,256]
//
// M[80][81] (odd stride, conflict-free).
// col scan: A[r][x] = seg-local col prefix, row segs {0-19|20-39|40-59|60-79}
// row scan: x-part-local prefix, parts {0-19|20-39|40-59|60-79}
// Qf(r,xi) = R[r][xi] + [xi>=20]R[r][19] + [xi>=40]R[r][39] + [xi>=60]R[r][59]
// g(y,x)   = Qf(r0) + [r0>=20]Qf(19) + [r0>=40]Qf(39) + [r0>=60]Qf(59)

#define Bn   64
#define Cn   256
#define Hn   80
#define Wn   80
#define Nn   100
#define SSTR 81
#define KPL  8
#define SEGR 20
#define PROD 320
#define TPB  352

__device__ __forceinline__ float Qf(const float* __restrict__ M, int r, int xi)
{
    const float* row = M + r * SSTR;
    float v = row[xi];
    if (xi >= 20) v += row[19];
    if (xi >= 40) v += row[39];
    if (xi >= 60) v += row[59];
    return v;
}

__device__ __forceinline__ float gfun(const float* __restrict__ M, int y, int x)
{
    if (y == 0 || x == 0) return 0.0f;
    const int r0 = y - 1;
    const int xi = x - 1;
    float v = Qf(M, r0, xi);
    if (r0 >= 20) v += Qf(M, 19, xi);
    if (r0 >= 40) v += Qf(M, 39, xi);
    if (r0 >= 60) v += Qf(M, 59, xi);
    return v;
}

__global__ __launch_bounds__(TPB, 4)
void roi_pool_v16_kernel(const float* __restrict__ fmap,
                         const float* __restrict__ boxes,
                         float* __restrict__ out)
{
    __shared__ float M[Hn * SSTR];       // 25,920 B
    __shared__ int4  BC[Nn];             // 1,600 B

    const int p0  = blockIdx.x * KPL;    // 8 consecutive planes, same b
    const int b   = p0 >> 8;
    const int c0  = p0 & 255;
    const int tid = threadIdx.x;

    const int col = tid % Wn;            // valid for tid < 320
    const int seg = tid / Wn;            // 0..3

    const float* __restrict__ gcol =
        fmap + (size_t)p0 * (Hn * Wn) + (seg * SEGR) * Wn + col;

    float v[SEGR];                       // staged next-plane column values

    // ---- Prologue: stage plane 0 | box coords ----------------------------
    if (tid < PROD) {
        #pragma unroll
        for (int i = 0; i < SEGR; ++i)
            v[i] = gcol[i * Wn];         // independent, coalesced LDGs
    } else {
        const float* __restrict__ bx = boxes + (size_t)b * (Nn * 4);
        for (int n = tid - PROD; n < Nn; n += TPB - PROD) {
            float4 bb = reinterpret_cast<const float4*>(bx)[n];
            // Match JAX exactly: IEEE div by 640, IEEE mul by 80, trunc, clip.
            int x1 = min(max((int)(__fmul_rn(__fdiv_rn(bb.x, 640.0f), 80.0f)), 0), Wn);
            int y1 = min(max((int)(__fmul_rn(__fdiv_rn(bb.y, 640.0f), 80.0f)), 0), Hn);
            int x2 = min(max((int)(__fmul_rn(__fdiv_rn(bb.z, 640.0f), 80.0f)), 0), Wn);
            int y2 = min(max((int)(__fmul_rn(__fdiv_rn(bb.w, 640.0f), 80.0f)), 0), Hn);
            BC[n] = make_int4(x1, y1, x2, y2);
        }
    }

    #pragma unroll 1
    for (int k = 0; k < KPL; ++k) {
        // ---- Column scan of staged regs -> prefix STS --------------------
        if (tid < PROD) {
            float acc = 0.0f;
            float* d = M + (seg * SEGR) * SSTR + col;
            #pragma unroll
            for (int i = 0; i < SEGR; ++i) {
                acc += v[i];
                d[i * SSTR] = acc;       // conflict-free STS
            }
        }
        __syncthreads();                 // prefix (and, at k=0, BC) visible

        // ---- Stage NEXT plane (flies under row scan + box phase) ---------
        if (k + 1 < KPL && tid < PROD) {
            const float* __restrict__ gn = gcol + (size_t)(k + 1) * (Hn * Wn);
            #pragma unroll
            for (int i = 0; i < SEGR; ++i)
                v[i] = gn[i * Wn];
        }

        // ---- Row scan in place (320 thr: 80 rows x 4 x-parts of 20) ------
        if (tid < PROD) {
            const int r    = tid % Hn;
            const int part = tid / Hn;   // 0..3
            float* d = M + r * SSTR + part * SEGR;
            float acc = 0.0f;
            #pragma unroll 10
            for (int i = 0; i < SEGR; ++i) {
                acc += d[i];
                d[i] = acc;
            }
        }
        __syncthreads();

        // ---- Box phase: O(1) stitched corners ----------------------------
        if (tid < Nn) {
            int4 q = BC[tid];
            float s = gfun(M, q.w, q.z) - gfun(M, q.y, q.z)
                    - gfun(M, q.w, q.x) + gfun(M, q.y, q.x);
            int dy = q.w - q.y;
            int dx = q.z - q.x;
            bool valid = (dy > 0) && (dx > 0);
            int  area  = max(dy * dx, 1);
            out[(size_t)b * (Nn * Cn) + (size_t)tid * Cn + (c0 + k)] =
                valid ? s / (float)area : 0.0f;
        }
        __syncthreads();                 // M free before next STS
    }
}

extern "C" void kernel_launch(void* const* d_in, const int* in_sizes, int n_in,
                              void* d_out, int out_size)
{
    const float* fmap  = (const float*)d_in[0];   // [64,256,80,80]
    const float* boxes = (const float*)d_in[1];   // [64,100,4]
    float*       out   = (float*)d_out;           // [64,100,256]

    (void)in_sizes; (void)n_in; (void)out_size;

    roi_pool_v16_kernel<<<(Bn * Cn) / KPL, TPB>>>(fmap, boxes, out);
}

// round 17
// speedup vs baseline: 1.1760x; 1.1760x over previous
#include <cuda_runtime.h>
#include <cuda_bf16.h>

// ROI mean-pool, v17: v15 cross-plane register-staged pipeline re-shaped to
// 320 threads (80 cols x 4 row-segments of 20) with a spill-free reg budget.
//
// fmap: [64,256,80,80] f32   boxes: [64,100,4]   out: [64,100,256]
//
// M[80][81] (odd stride, conflict-free in every phase).
// col scan (regs->STS): A[r][x] = seg-local col prefix, segs {0-19|20-39|40-59|60-79}
// row scan (in place):  x-part-local prefix, parts {0-19|20-39|40-59|60-79}
// Qf(r,xi) = R[r][xi] + [xi>=20]R[r][19] + [xi>=40]R[r][39] + [xi>=60]R[r][59]
// g(y,x)   = Qf(r0) + [r0>=20]Qf(19) + [r0>=40]Qf(39) + [r0>=60]Qf(59), r0=y-1

#define Bn   64
#define Cn   256
#define Hn   80
#define Wn   80
#define Nn   100
#define SSTR 81
#define KPL  8
#define SEGR 20
#define TPB  320

__device__ __forceinline__ float Qf(const float* __restrict__ M, int r, int xi)
{
    const float* row = M + r * SSTR;
    float v = row[xi];
    if (xi >= 20) v += row[19];
    if (xi >= 40) v += row[39];
    if (xi >= 60) v += row[59];
    return v;
}

__device__ __forceinline__ float gfun(const float* __restrict__ M, int y, int x)
{
    if (y == 0 || x == 0) return 0.0f;
    const int r0 = y - 1;
    const int xi = x - 1;
    float v = Qf(M, r0, xi);
    if (r0 >= 20) v += Qf(M, 19, xi);
    if (r0 >= 40) v += Qf(M, 39, xi);
    if (r0 >= 60) v += Qf(M, 59, xi);
    return v;
}

__global__ __launch_bounds__(TPB, 4)   // reg cap 51: fits 20-elt array w/o spill
void roi_pool_v17_kernel(const float* __restrict__ fmap,
                         const float* __restrict__ boxes,
                         float* __restrict__ out)
{
    __shared__ float M[Hn * SSTR];       // 25,920 B
    __shared__ int4  BC[Nn];             // 1,600 B

    const int p0  = blockIdx.x * KPL;    // 8 consecutive planes, same b
    const int b   = p0 >> 8;
    const int c0  = p0 & 255;
    const int tid = threadIdx.x;

    const int col = tid % Wn;
    const int seg = tid / Wn;            // 0..3 (all 320 threads are producers)

    const float* __restrict__ gcol =
        fmap + (size_t)p0 * (Hn * Wn) + (seg * SEGR) * Wn + col;

    float v[SEGR];                       // staged next-plane column values

    // ---- Prologue: issue plane-0 staging, then (overlapped) box coords ---
    #pragma unroll
    for (int i = 0; i < SEGR; ++i)
        v[i] = gcol[i * Wn];             // independent, coalesced LDGs

    if (tid < Nn) {
        float4 bb = reinterpret_cast<const float4*>(boxes + (size_t)b * (Nn * 4))[tid];
        // Match JAX exactly: IEEE div by 640, IEEE mul by 80, trunc, clip.
        int x1 = min(max((int)(__fmul_rn(__fdiv_rn(bb.x, 640.0f), 80.0f)), 0), Wn);
        int y1 = min(max((int)(__fmul_rn(__fdiv_rn(bb.y, 640.0f), 80.0f)), 0), Hn);
        int x2 = min(max((int)(__fmul_rn(__fdiv_rn(bb.z, 640.0f), 80.0f)), 0), Wn);
        int y2 = min(max((int)(__fmul_rn(__fdiv_rn(bb.w, 640.0f), 80.0f)), 0), Hn);
        BC[tid] = make_int4(x1, y1, x2, y2);
    }

    #pragma unroll 1
    for (int k = 0; k < KPL; ++k) {
        // ---- Column scan of staged regs -> prefix STS --------------------
        {
            float acc = 0.0f;
            float* d = M + (seg * SEGR) * SSTR + col;
            #pragma unroll
            for (int i = 0; i < SEGR; ++i) {
                acc += v[i];
                d[i * SSTR] = acc;       // conflict-free STS
            }
        }
        __syncthreads();                 // prefix (and, at k=0, BC) visible

        // ---- Stage NEXT plane (flies under row scan + box phase) ---------
        if (k + 1 < KPL) {
            const float* __restrict__ gn = gcol + (size_t)(k + 1) * (Hn * Wn);
            #pragma unroll
            for (int i = 0; i < SEGR; ++i)
                v[i] = gn[i * Wn];
        }

        // ---- Row scan in place (320 thr: 80 rows x 4 x-parts of 20) ------
        {
            const int r    = tid % Hn;
            const int part = tid / Hn;   // 0..3
            float* d = M + r * SSTR + part * SEGR;
            float acc = 0.0f;
            #pragma unroll 10
            for (int i = 0; i < SEGR; ++i) {
                acc += d[i];
                d[i] = acc;
            }
        }
        __syncthreads();

        // ---- Box phase: O(1) stitched corners ----------------------------
        if (tid < Nn) {
            int4 q = BC[tid];
            float s = gfun(M, q.w, q.z) - gfun(M, q.y, q.z)
                    - gfun(M, q.w, q.x) + gfun(M, q.y, q.x);
            int dy = q.w - q.y;
            int dx = q.z - q.x;
            bool valid = (dy > 0) && (dx > 0);
            int  area  = max(dy * dx, 1);
            out[(size_t)b * (Nn * Cn) + (size_t)tid * Cn + (c0 + k)] =
                valid ? s / (float)area : 0.0f;
        }
        __syncthreads();                 // M free before next STS
    }
}

extern "C" void kernel_launch(void* const* d_in, const int* in_sizes, int n_in,
                              void* d_out, int out_size)
{
    const float* fmap  = (const float*)d_in[0];   // [64,256,80,80]
    const float* boxes = (const float*)d_in[1];   // [64,100,4]
    float*       out   = (float*)d_out;           // [64,100,256]

    (void)in_sizes; (void)n_in; (void)out_size;

    roi_pool_v17_kernel<<<(Bn * Cn) / KPL, TPB>>>(fmap, boxes, out);
}